// round 12
// baseline (speedup 1.0000x reference)
#include <cuda_runtime.h>
#include <math.h>
#include <float.h>

#define B 256
#define N 2048
#define M 64
#define C 512
#define OUTD 198   // 3*M + 6

__device__ __forceinline__ float softplus_f(float x) {
    return (x > 20.f) ? x : log1pf(expf(x));
}
__device__ __forceinline__ float sigmoid_f(float x) {
    return 1.f / (1.f + __expf(-x));
}

__device__ __forceinline__ float blockReduce1024(float v, float* red, bool is_max) {
    int lane = threadIdx.x & 31, wid = threadIdx.x >> 5;
    #pragma unroll
    for (int o = 16; o; o >>= 1) {
        float t = __shfl_xor_sync(0xffffffffu, v, o);
        v = is_max ? fmaxf(v, t) : (v + t);
    }
    if (lane == 0) red[wid] = v;
    __syncthreads();
    if (wid == 0) {
        float r = red[lane];
        #pragma unroll
        for (int o = 16; o; o >>= 1) {
            float t = __shfl_xor_sync(0xffffffffu, r, o);
            r = is_max ? fmaxf(r, t) : (r + t);
        }
        if (lane == 0) red[0] = r;
    }
    __syncthreads();
    float out = red[0];
    __syncthreads();
    return out;
}

// Warp-level dot of W row j with sh_h, float4 loads. Full sum on lane 0.
__device__ __forceinline__ float wdot(const float* __restrict__ Wm, int j,
                                      const float* sh_h, int lane) {
    const float4* wr4 = (const float4*)(Wm + (size_t)j * C);
    const float4* hh4 = (const float4*)sh_h;
    float acc = 0.f;
    #pragma unroll
    for (int r = 0; r < 4; r++) {
        float4 wv = wr4[lane + 32 * r];
        float4 hv = hh4[lane + 32 * r];
        acc += wv.x * hv.x + wv.y * hv.y + wv.z * hv.z + wv.w * hv.w;
    }
    #pragma unroll
    for (int o = 16; o; o >>= 1) acc += __shfl_xor_sync(0xffffffffu, acc, o);
    return acc;
}

// ---------------------------------------------------------------------------
// Single fused kernel: one block per batch, 1024 threads, 2 blocks/SM.
//  Stage A: projection rows [0,70) -> k, beta, g, s, gamma, knorm.
//  Phase 1: warps 0..27 stream memory -> scores (fully unrolled, MLP 4);
//           warps 28..31 concurrently compute rows [70,198) -> e, a with
//           4-way interleaved dots (hidden under phase 1).
//  Phase 2: softmax + gate + circular shift + sharpen -> w.
//  Phase 3: erase/add write, forward order, unroll 4 (the R5 engine).
// ---------------------------------------------------------------------------
__global__ void __launch_bounds__(1024, 2)
k_all(const float* __restrict__ h,
      const float* __restrict__ w_prev,
      const float* __restrict__ memory,
      const float* __restrict__ Wm,
      const float* __restrict__ bias,
      float* __restrict__ w_out,
      float* __restrict__ mem_out) {
    int b = blockIdx.x;
    int tid = threadIdx.x;
    int warp = tid >> 5, lane = tid & 31;

    __shared__ float s_sc[N];     // scores, then reused as final w
    __shared__ float s_w[N];      // gated weights
    __shared__ float sh_h[C];     // this batch's h
    __shared__ float so[72];      // projection rows [0,70)
    __shared__ float sk[64];      // k + 1e-16
    __shared__ float sea[128];    // e[0..63], a[64..127]
    __shared__ float ssc[7];      // beta,g,gamma,s0,s1,s2,knorm
    __shared__ float red[32];

    // ---- load h ----
    if (tid < 128) ((float4*)sh_h)[tid] = ((const float4*)(h + (size_t)b * C))[tid];
    __syncthreads();

    // ---- Stage A: projection rows [0,70) (<=3 rows per warp) ----
    for (int j = warp; j < 70; j += 32) {
        float acc = wdot(Wm, j, sh_h, lane);
        if (lane == 0) so[j] = acc + bias[j];
    }
    __syncthreads();

    if (tid < 64) sk[tid] = so[tid] + 1e-16f;
    if (tid == 64) {
        ssc[0] = softplus_f(so[64]);            // beta
        ssc[1] = sigmoid_f(so[65]);             // g
        ssc[2] = 1.f + softplus_f(so[69]);      // gamma
        float s0 = so[66], s1 = so[67], s2 = so[68];
        float mx = fmaxf(s0, fmaxf(s1, s2));
        float e0 = __expf(s0 - mx), e1 = __expf(s1 - mx), e2 = __expf(s2 - mx);
        float inv = 1.f / (e0 + e1 + e2);
        ssc[3] = e0 * inv; ssc[4] = e1 * inv; ssc[5] = e2 * inv;
    }
    if (warp == 1) {   // ||k + 1e-16||
        float v0 = so[lane] + 1e-16f;
        float v1 = so[lane + 32] + 1e-16f;
        float acc = v0 * v0 + v1 * v1;
        #pragma unroll
        for (int o = 16; o; o >>= 1) acc += __shfl_xor_sync(0xffffffffu, acc, o);
        if (lane == 0) ssc[6] = sqrtf(acc);
    }
    __syncthreads();

    // ---- Phase 1 (warps 0..27) || Stage B e/a projection (warps 28..31) ----
    if (warp < 28) {
        int sub = lane >> 3;      // 0..3
        int q = lane & 7;         // chunk within row
        float4 k0 = ((const float4*)sk)[q * 2];
        float4 k1 = ((const float4*)sk)[q * 2 + 1];
        float beta = ssc[0], knorm = ssc[6];

        const float4* base = (const float4*)(memory + (size_t)b * N * M);
        // 28 warps x 4 rows = 112 rows/iter; 18 iters cover rows [0,2016),
        // tail rows [2016,2048) by warps 0..7.
        #pragma unroll 2
        for (int it = 0; it < 18; it++) {
            int row = it * 112 + warp * 4 + sub;
            const float4* mp = base + (size_t)row * 16 + q * 2;
            float4 m0 = mp[0];
            float4 m1 = mp[1];
            float x0 = m0.x + 1e-16f, x1 = m0.y + 1e-16f, x2 = m0.z + 1e-16f, x3 = m0.w + 1e-16f;
            float y0 = m1.x + 1e-16f, y1 = m1.y + 1e-16f, y2 = m1.z + 1e-16f, y3 = m1.w + 1e-16f;
            float dot = x0 * k0.x + x1 * k0.y + x2 * k0.z + x3 * k0.w
                      + y0 * k1.x + y1 * k1.y + y2 * k1.z + y3 * k1.w;
            float nrm = x0 * x0 + x1 * x1 + x2 * x2 + x3 * x3
                      + y0 * y0 + y1 * y1 + y2 * y2 + y3 * y3;
            #pragma unroll
            for (int o = 4; o; o >>= 1) {
                dot += __shfl_xor_sync(0xffffffffu, dot, o);
                nrm += __shfl_xor_sync(0xffffffffu, nrm, o);
            }
            if (q == 0) {
                float denom = fmaxf(sqrtf(nrm) * knorm, 1e-8f);
                s_sc[row] = beta * dot / denom;
            }
        }
        if (warp < 8) {   // tail rows [2016, 2048)
            int row = 2016 + warp * 4 + sub;
            const float4* mp = base + (size_t)row * 16 + q * 2;
            float4 m0 = mp[0];
            float4 m1 = mp[1];
            float x0 = m0.x + 1e-16f, x1 = m0.y + 1e-16f, x2 = m0.z + 1e-16f, x3 = m0.w + 1e-16f;
            float y0 = m1.x + 1e-16f, y1 = m1.y + 1e-16f, y2 = m1.z + 1e-16f, y3 = m1.w + 1e-16f;
            float dot = x0 * k0.x + x1 * k0.y + x2 * k0.z + x3 * k0.w
                      + y0 * k1.x + y1 * k1.y + y2 * k1.z + y3 * k1.w;
            float nrm = x0 * x0 + x1 * x1 + x2 * x2 + x3 * x3
                      + y0 * y0 + y1 * y1 + y2 * y2 + y3 * y3;
            #pragma unroll
            for (int o = 4; o; o >>= 1) {
                dot += __shfl_xor_sync(0xffffffffu, dot, o);
                nrm += __shfl_xor_sync(0xffffffffu, nrm, o);
            }
            if (q == 0) {
                float denom = fmaxf(sqrtf(nrm) * knorm, 1e-8f);
                s_sc[row] = beta * dot / denom;
            }
        }
    } else {
        // Stage B: 128 rows over 4 warps, 4-way interleaved (16 loads in
        // flight per group, 8 groups) -> ~6us, hidden under phase 1.
        int w4 = warp - 28;   // 0..3
        const float4* hh4 = (const float4*)sh_h;
        for (int g = 0; g < 8; g++) {
            int jb = 70 + w4 + 16 * g;    // rows jb, jb+4, jb+8, jb+12
            float acc[4] = {0.f, 0.f, 0.f, 0.f};
            #pragma unroll
            for (int r = 0; r < 4; r++) {
                float4 hv = hh4[lane + 32 * r];
                #pragma unroll
                for (int u = 0; u < 4; u++) {
                    const float4* wr4 = (const float4*)(Wm + (size_t)(jb + 4 * u) * C);
                    float4 wv = wr4[lane + 32 * r];
                    acc[u] += wv.x * hv.x + wv.y * hv.y + wv.z * hv.z + wv.w * hv.w;
                }
            }
            #pragma unroll
            for (int u = 0; u < 4; u++) {
                #pragma unroll
                for (int o = 16; o; o >>= 1)
                    acc[u] += __shfl_xor_sync(0xffffffffu, acc[u], o);
            }
            if (lane == 0) {
                #pragma unroll
                for (int u = 0; u < 4; u++) {
                    int j = jb + 4 * u;
                    float v = acc[u] + bias[j];
                    if (j < 134) sea[j - 70] = sigmoid_f(v);       // e
                    else         sea[64 + (j - 134)] = v;          // a
                }
            }
        }
    }
    __syncthreads();

    // ---- Phase 2: softmax + gate + shift + sharpen ----
    {
        float v[2];
        v[0] = s_sc[tid]; v[1] = s_sc[tid + 1024];
        float mx = fmaxf(v[0], v[1]);
        mx = blockReduce1024(mx, red, true);

        float sum = 0.f;
        #pragma unroll
        for (int i = 0; i < 2; i++) { v[i] = __expf(v[i] - mx); sum += v[i]; }
        sum = blockReduce1024(sum, red, false);
        float inv = 1.f / sum;

        float g = ssc[1];
        #pragma unroll
        for (int i = 0; i < 2; i++) {
            int idx = tid + i * 1024;
            s_w[idx] = g * (v[i] * inv) + (1.f - g) * w_prev[(size_t)b * N + idx];
        }
        __syncthreads();

        float s0 = ssc[3], s1 = ssc[4], s2 = ssc[5], gamma = ssc[2];
        float u[2];
        float psum = 0.f;
        #pragma unroll
        for (int i = 0; i < 2; i++) {
            int idx = tid + i * 1024;
            float wt = s_w[(idx + N - 1) & (N - 1)] * s0 + s_w[idx] * s1
                     + s_w[(idx + 1) & (N - 1)] * s2;
            float ws = __powf(wt, gamma);   // wt >= 0
            u[i] = ws; psum += ws;
        }
        psum = blockReduce1024(psum, red, false);
        float invp = 1.f / (psum + 1e-16f);
        #pragma unroll
        for (int i = 0; i < 2; i++) {
            int idx = tid + i * 1024;
            float wf = u[i] * invp;
            s_sc[idx] = wf;                        // final w, reuse s_sc
            w_out[(size_t)b * N + idx] = wf;
        }
    }
    __syncthreads();

    // ---- Phase 3: erase/add write (R5 engine: forward, unroll 4) ----
    {
        const float4* min4 = (const float4*)(memory + (size_t)b * N * M);
        float4* mout4 = (float4*)(mem_out + (size_t)b * N * M);
        int m4 = tid & 15;                          // fixed across iterations
        float4 e4 = ((const float4*)sea)[m4];
        float4 a4 = ((const float4*)(sea + 64))[m4];

        #pragma unroll 4
        for (int i = tid; i < N * M / 4; i += 1024) {
            int row = i >> 4;
            float wv = s_sc[row];
            float4 m = __ldcs(min4 + i);
            float4 o;
            o.x = m.x * (1.f - wv * e4.x) + wv * a4.x;
            o.y = m.y * (1.f - wv * e4.y) + wv * a4.y;
            o.z = m.z * (1.f - wv * e4.z) + wv * a4.z;
            o.w = m.w * (1.f - wv * e4.w) + wv * a4.w;
            __stcs(mout4 + i, o);
        }
    }
}

// ---------------------------------------------------------------------------
extern "C" void kernel_launch(void* const* d_in, const int* in_sizes, int n_in,
                              void* d_out, int out_size) {
    const float* h      = (const float*)d_in[0];
    const float* w_prev = (const float*)d_in[1];
    const float* memory = (const float*)d_in[2];
    const float* Wm     = (const float*)d_in[3];
    const float* bias   = (const float*)d_in[4];

    float* w_out   = (float*)d_out;                     // [B, N]
    float* mem_out = (float*)d_out + (size_t)B * N;     // [B, N, M]

    k_all<<<B, 1024>>>(h, w_prev, memory, Wm, bias, w_out, mem_out);
}

// round 13
// speedup vs baseline: 1.2093x; 1.2093x over previous
#include <cuda_runtime.h>
#include <math.h>
#include <float.h>

#define B 256
#define N 2048
#define M 64
#define C 512
#define OUTD 198       // 3*M + 6
#define STASH_ROWS 768 // rows of the memory tile kept in smem (192 KB)

__device__ __forceinline__ float softplus_f(float x) {
    return (x > 20.f) ? x : log1pf(expf(x));
}
__device__ __forceinline__ float sigmoid_f(float x) {
    return 1.f / (1.f + __expf(-x));
}

__device__ __forceinline__ float blockReduce1024(float v, float* red, bool is_max) {
    int lane = threadIdx.x & 31, wid = threadIdx.x >> 5;
    #pragma unroll
    for (int o = 16; o; o >>= 1) {
        float t = __shfl_xor_sync(0xffffffffu, v, o);
        v = is_max ? fmaxf(v, t) : (v + t);
    }
    if (lane == 0) red[wid] = v;
    __syncthreads();
    if (wid == 0) {
        float r = red[lane];
        #pragma unroll
        for (int o = 16; o; o >>= 1) {
            float t = __shfl_xor_sync(0xffffffffu, r, o);
            r = is_max ? fmaxf(r, t) : (r + t);
        }
        if (lane == 0) red[0] = r;
    }
    __syncthreads();
    float out = red[0];
    __syncthreads();
    return out;
}

// Warp-level dot of W row j with sh_h, float4 loads. Full sum on lane 0.
__device__ __forceinline__ float wdot(const float* __restrict__ Wm, int j,
                                      const float* sh_h, int lane) {
    const float4* wr4 = (const float4*)(Wm + (size_t)j * C);
    const float4* hh4 = (const float4*)sh_h;
    float acc = 0.f;
    #pragma unroll
    for (int r = 0; r < 4; r++) {
        float4 wv = wr4[lane + 32 * r];
        float4 hv = hh4[lane + 32 * r];
        acc += wv.x * hv.x + wv.y * hv.y + wv.z * hv.z + wv.w * hv.w;
    }
    #pragma unroll
    for (int o = 16; o; o >>= 1) acc += __shfl_xor_sync(0xffffffffu, acc, o);
    return acc;
}

// ---------------------------------------------------------------------------
// Single fused kernel: one block per batch, 1024 threads, 1 block/SM
// (static ~20 KB + dynamic 192 KB stash). 64-reg budget -> deep MLP:
//  Stage A: projection rows [0,70) -> k, beta, g, s, gamma, knorm.
//  Phase 1: 32 warps stream memory -> scores, 8 float4 loads in flight per
//           thread (grouped x4); rows < STASH_ROWS copied to the smem stash.
//  Phase 2: softmax + gate + circular shift + sharpen -> w.
//  Stage B: projection rows [70,198) -> e, a.
//  Phase 3: stashed rows from smem; remaining rows re-read (reverse order,
//           148x512KB = 76 MB < L2 -> mostly L2 hits), unroll 8 equivalent.
// ---------------------------------------------------------------------------
__global__ void __launch_bounds__(1024, 1)
k_all(const float* __restrict__ h,
      const float* __restrict__ w_prev,
      const float* __restrict__ memory,
      const float* __restrict__ Wm,
      const float* __restrict__ bias,
      float* __restrict__ w_out,
      float* __restrict__ mem_out) {
    extern __shared__ float stash[];   // STASH_ROWS * 64 floats = 192 KB

    int b = blockIdx.x;
    int tid = threadIdx.x;
    int warp = tid >> 5, lane = tid & 31;

    __shared__ float s_sc[N];     // scores, then reused as final w
    __shared__ float s_w[N];      // gated weights
    __shared__ float sh_h[C];     // this batch's h
    __shared__ float so[72];      // projection rows [0,70)
    __shared__ float sk[64];      // k + 1e-16
    __shared__ float sea[128];    // e[0..63], a[64..127]
    __shared__ float ssc[7];      // beta,g,gamma,s0,s1,s2,knorm
    __shared__ float red[32];

    // ---- load h ----
    if (tid < 128) ((float4*)sh_h)[tid] = ((const float4*)(h + (size_t)b * C))[tid];
    __syncthreads();

    // ---- Stage A: projection rows [0,70) (<=3 rows per warp) ----
    for (int j = warp; j < 70; j += 32) {
        float acc = wdot(Wm, j, sh_h, lane);
        if (lane == 0) so[j] = acc + bias[j];
    }
    __syncthreads();

    if (tid < 64) sk[tid] = so[tid] + 1e-16f;
    if (tid == 64) {
        ssc[0] = softplus_f(so[64]);            // beta
        ssc[1] = sigmoid_f(so[65]);             // g
        ssc[2] = 1.f + softplus_f(so[69]);      // gamma
        float s0 = so[66], s1 = so[67], s2 = so[68];
        float mx = fmaxf(s0, fmaxf(s1, s2));
        float e0 = __expf(s0 - mx), e1 = __expf(s1 - mx), e2 = __expf(s2 - mx);
        float inv = 1.f / (e0 + e1 + e2);
        ssc[3] = e0 * inv; ssc[4] = e1 * inv; ssc[5] = e2 * inv;
    }
    if (warp == 1) {   // ||k + 1e-16||
        float v0 = so[lane] + 1e-16f;
        float v1 = so[lane + 32] + 1e-16f;
        float acc = v0 * v0 + v1 * v1;
        #pragma unroll
        for (int o = 16; o; o >>= 1) acc += __shfl_xor_sync(0xffffffffu, acc, o);
        if (lane == 0) ssc[6] = sqrtf(acc);
    }
    __syncthreads();

    // ---- Phase 1: content scores, 8 loads in flight per thread ----
    {
        int sub = lane >> 3;      // 0..3
        int q = lane & 7;         // chunk within row
        float4 k0 = ((const float4*)sk)[q * 2];
        float4 k1 = ((const float4*)sk)[q * 2 + 1];
        float beta = ssc[0], knorm = ssc[6];

        const float4* base = (const float4*)(memory + (size_t)b * N * M);
        float4* st4 = (float4*)stash;
        // 16 logical iterations (128 rows each), grouped 4-at-a-time.
        #pragma unroll
        for (int g = 0; g < 4; g++) {
            float4 mm[4][2];
            #pragma unroll
            for (int u = 0; u < 4; u++) {
                int row = (g * 4 + u) * 128 + warp * 4 + sub;
                const float4* mp = base + (size_t)row * 16 + q * 2;
                mm[u][0] = mp[0];
                mm[u][1] = mp[1];
            }
            #pragma unroll
            for (int u = 0; u < 4; u++) {
                int row = (g * 4 + u) * 128 + warp * 4 + sub;
                if ((g * 4 + u) * 128 < STASH_ROWS) {   // compile-time
                    st4[row * 16 + q * 2]     = mm[u][0];
                    st4[row * 16 + q * 2 + 1] = mm[u][1];
                }
                float x0 = mm[u][0].x + 1e-16f, x1 = mm[u][0].y + 1e-16f;
                float x2 = mm[u][0].z + 1e-16f, x3 = mm[u][0].w + 1e-16f;
                float y0 = mm[u][1].x + 1e-16f, y1 = mm[u][1].y + 1e-16f;
                float y2 = mm[u][1].z + 1e-16f, y3 = mm[u][1].w + 1e-16f;
                float dot = x0 * k0.x + x1 * k0.y + x2 * k0.z + x3 * k0.w
                          + y0 * k1.x + y1 * k1.y + y2 * k1.z + y3 * k1.w;
                float nrm = x0 * x0 + x1 * x1 + x2 * x2 + x3 * x3
                          + y0 * y0 + y1 * y1 + y2 * y2 + y3 * y3;
                #pragma unroll
                for (int o = 4; o; o >>= 1) {
                    dot += __shfl_xor_sync(0xffffffffu, dot, o);
                    nrm += __shfl_xor_sync(0xffffffffu, nrm, o);
                }
                if (q == 0) {
                    float denom = fmaxf(sqrtf(nrm) * knorm, 1e-8f);
                    s_sc[row] = beta * dot / denom;
                }
            }
        }
    }
    __syncthreads();

    // ---- Phase 2: softmax + gate + shift + sharpen ----
    {
        float v[2];
        v[0] = s_sc[tid]; v[1] = s_sc[tid + 1024];
        float mx = fmaxf(v[0], v[1]);
        mx = blockReduce1024(mx, red, true);

        float sum = 0.f;
        #pragma unroll
        for (int i = 0; i < 2; i++) { v[i] = __expf(v[i] - mx); sum += v[i]; }
        sum = blockReduce1024(sum, red, false);
        float inv = 1.f / sum;

        float g = ssc[1];
        #pragma unroll
        for (int i = 0; i < 2; i++) {
            int idx = tid + i * 1024;
            s_w[idx] = g * (v[i] * inv) + (1.f - g) * w_prev[(size_t)b * N + idx];
        }
        __syncthreads();

        float s0 = ssc[3], s1 = ssc[4], s2 = ssc[5], gamma = ssc[2];
        float u[2];
        float psum = 0.f;
        #pragma unroll
        for (int i = 0; i < 2; i++) {
            int idx = tid + i * 1024;
            float wt = s_w[(idx + N - 1) & (N - 1)] * s0 + s_w[idx] * s1
                     + s_w[(idx + 1) & (N - 1)] * s2;
            float ws = __powf(wt, gamma);   // wt >= 0
            u[i] = ws; psum += ws;
        }
        psum = blockReduce1024(psum, red, false);
        float invp = 1.f / (psum + 1e-16f);
        #pragma unroll
        for (int i = 0; i < 2; i++) {
            int idx = tid + i * 1024;
            float wf = u[i] * invp;
            s_sc[idx] = wf;                        // final w, reuse s_sc
            w_out[(size_t)b * N + idx] = wf;
        }
    }
    __syncthreads();

    // ---- Stage B: projection rows [70,198) -> e, a (4 rows/warp) ----
    for (int j = 70 + warp; j < OUTD; j += 32) {
        float acc = wdot(Wm, j, sh_h, lane);
        if (lane == 0) {
            float v = acc + bias[j];
            if (j < 134) sea[j - 70] = sigmoid_f(v);       // e
            else         sea[64 + (j - 134)] = v;          // a
        }
    }
    __syncthreads();

    // ---- Phase 3: erase/add write ----
    {
        const float4* min4 = (const float4*)(memory + (size_t)b * N * M);
        float4* mout4 = (float4*)(mem_out + (size_t)b * N * M);
        const float4* st4 = (const float4*)stash;
        int m4 = tid & 15;
        float4 e4 = ((const float4*)sea)[m4];
        float4 a4 = ((const float4*)(sea + 64))[m4];

        // 3a: stashed rows [0, STASH_ROWS): smem reads. 12 iterations.
        #pragma unroll 4
        for (int it = 0; it < STASH_ROWS * 16 / 1024; it++) {
            int i = it * 1024 + tid;
            float wv = s_sc[i >> 4];
            float4 m = st4[i];
            float4 o;
            o.x = m.x * (1.f - wv * e4.x) + wv * a4.x;
            o.y = m.y * (1.f - wv * e4.y) + wv * a4.y;
            o.z = m.z * (1.f - wv * e4.z) + wv * a4.z;
            o.w = m.w * (1.f - wv * e4.w) + wv * a4.w;
            __stcs(mout4 + i, o);
        }
        // 3b: rows [STASH_ROWS, N): re-read global, reverse, deep unroll.
        #pragma unroll 4
        for (int it = (N * M / 4) / 1024 - 1; it >= STASH_ROWS * 16 / 1024; it--) {
            int i = it * 1024 + tid;
            float wv = s_sc[i >> 4];
            float4 m = __ldcs(min4 + i);
            float4 o;
            o.x = m.x * (1.f - wv * e4.x) + wv * a4.x;
            o.y = m.y * (1.f - wv * e4.y) + wv * a4.y;
            o.z = m.z * (1.f - wv * e4.z) + wv * a4.z;
            o.w = m.w * (1.f - wv * e4.w) + wv * a4.w;
            __stcs(mout4 + i, o);
        }
    }
}

// ---------------------------------------------------------------------------
extern "C" void kernel_launch(void* const* d_in, const int* in_sizes, int n_in,
                              void* d_out, int out_size) {
    const float* h      = (const float*)d_in[0];
    const float* w_prev = (const float*)d_in[1];
    const float* memory = (const float*)d_in[2];
    const float* Wm     = (const float*)d_in[3];
    const float* bias   = (const float*)d_in[4];

    float* w_out   = (float*)d_out;                     // [B, N]
    float* mem_out = (float*)d_out + (size_t)B * N;     // [B, N, M]

    const int stash_bytes = STASH_ROWS * M * sizeof(float);   // 192 KB
    cudaFuncSetAttribute(k_all, cudaFuncAttributeMaxDynamicSharedMemorySize,
                         stash_bytes);
    k_all<<<B, 1024, stash_bytes>>>(h, w_prev, memory, Wm, bias, w_out, mem_out);
}

// round 14
// speedup vs baseline: 1.3522x; 1.1181x over previous
#include <cuda_runtime.h>
#include <math.h>
#include <float.h>

#define B 256
#define N 2048
#define M 64
#define C 512
#define OUTD 198       // 3*M + 6
#define STASH_ROWS 640 // rows of the memory tile kept in smem (160 KB)

__device__ __forceinline__ float softplus_f(float x) {
    return (x > 20.f) ? x : log1pf(expf(x));
}
__device__ __forceinline__ float sigmoid_f(float x) {
    return 1.f / (1.f + __expf(-x));
}

__device__ __forceinline__ float blockReduce1024(float v, float* red, bool is_max) {
    int lane = threadIdx.x & 31, wid = threadIdx.x >> 5;
    #pragma unroll
    for (int o = 16; o; o >>= 1) {
        float t = __shfl_xor_sync(0xffffffffu, v, o);
        v = is_max ? fmaxf(v, t) : (v + t);
    }
    if (lane == 0) red[wid] = v;
    __syncthreads();
    if (wid == 0) {
        float r = red[lane];
        #pragma unroll
        for (int o = 16; o; o >>= 1) {
            float t = __shfl_xor_sync(0xffffffffu, r, o);
            r = is_max ? fmaxf(r, t) : (r + t);
        }
        if (lane == 0) red[0] = r;
    }
    __syncthreads();
    float out = red[0];
    __syncthreads();
    return out;
}

// Warp-level dot of W row j with sh_h, float4 loads. Full sum on lane 0.
__device__ __forceinline__ float wdot(const float* __restrict__ Wm, int j,
                                      const float* sh_h, int lane) {
    const float4* wr4 = (const float4*)(Wm + (size_t)j * C);
    const float4* hh4 = (const float4*)sh_h;
    float acc = 0.f;
    #pragma unroll
    for (int r = 0; r < 4; r++) {
        float4 wv = wr4[lane + 32 * r];
        float4 hv = hh4[lane + 32 * r];
        acc += wv.x * hv.x + wv.y * hv.y + wv.z * hv.z + wv.w * hv.w;
    }
    #pragma unroll
    for (int o = 16; o; o >>= 1) acc += __shfl_xor_sync(0xffffffffu, acc, o);
    return acc;
}

// ---------------------------------------------------------------------------
// Single fused kernel: one block per batch, 1024 threads, 1 block/SM
// (static ~20 KB + dynamic 160 KB stash).
//  Stage A: projection rows [0,70) -> k, beta, g, s, gamma, knorm.
//  Phase 1: 32 warps stream memory -> scores (no mem-side epsilon);
//           rows < STASH_ROWS copied to the smem stash.
//  Phase 2: softmax + gate + circular shift + sharpen -> w.
//  Stage B: projection rows [70,198) -> e, a.
//  Phase 3: 3b FIRST — global re-read of rows [STASH_ROWS,N) in REVERSE
//           (L2-freshest first) with unroll 4; then 3a from the smem stash.
// ---------------------------------------------------------------------------
__global__ void __launch_bounds__(1024, 1)
k_all(const float* __restrict__ h,
      const float* __restrict__ w_prev,
      const float* __restrict__ memory,
      const float* __restrict__ Wm,
      const float* __restrict__ bias,
      float* __restrict__ w_out,
      float* __restrict__ mem_out) {
    extern __shared__ float stash[];   // STASH_ROWS * 64 floats = 160 KB

    int b = blockIdx.x;
    int tid = threadIdx.x;
    int warp = tid >> 5, lane = tid & 31;

    __shared__ float s_sc[N];     // scores, then reused as final w
    __shared__ float s_w[N];      // gated weights
    __shared__ float sh_h[C];     // this batch's h
    __shared__ float so[72];      // projection rows [0,70)
    __shared__ float sk[64];      // k + 1e-16
    __shared__ float sea[128];    // e[0..63], a[64..127]
    __shared__ float ssc[7];      // beta,g,gamma,s0,s1,s2,knorm
    __shared__ float red[32];

    // ---- load h ----
    if (tid < 128) ((float4*)sh_h)[tid] = ((const float4*)(h + (size_t)b * C))[tid];
    __syncthreads();

    // ---- Stage A: projection rows [0,70) (<=3 rows per warp) ----
    for (int j = warp; j < 70; j += 32) {
        float acc = wdot(Wm, j, sh_h, lane);
        if (lane == 0) so[j] = acc + bias[j];
    }
    __syncthreads();

    if (tid < 64) sk[tid] = so[tid] + 1e-16f;
    if (tid == 64) {
        ssc[0] = softplus_f(so[64]);            // beta
        ssc[1] = sigmoid_f(so[65]);             // g
        ssc[2] = 1.f + softplus_f(so[69]);      // gamma
        float s0 = so[66], s1 = so[67], s2 = so[68];
        float mx = fmaxf(s0, fmaxf(s1, s2));
        float e0 = __expf(s0 - mx), e1 = __expf(s1 - mx), e2 = __expf(s2 - mx);
        float inv = 1.f / (e0 + e1 + e2);
        ssc[3] = e0 * inv; ssc[4] = e1 * inv; ssc[5] = e2 * inv;
    }
    if (warp == 1) {   // ||k + 1e-16||
        float v0 = so[lane] + 1e-16f;
        float v1 = so[lane + 32] + 1e-16f;
        float acc = v0 * v0 + v1 * v1;
        #pragma unroll
        for (int o = 16; o; o >>= 1) acc += __shfl_xor_sync(0xffffffffu, acc, o);
        if (lane == 0) ssc[6] = sqrtf(acc);
    }
    __syncthreads();

    // ---- Phase 1: content scores (R8 engine; mem-side epsilon dropped:
    //      its contribution ~1e-18 rel << 1e-3 tolerance) ----
    {
        int sub = lane >> 3;      // 0..3
        int q = lane & 7;         // chunk within row
        float4 k0 = ((const float4*)sk)[q * 2];
        float4 k1 = ((const float4*)sk)[q * 2 + 1];
        float beta = ssc[0], knorm = ssc[6];

        const float4* base = (const float4*)(memory + (size_t)b * N * M);
        float4* st4 = (float4*)stash;
        // 32 warps x 4 rows = 128 rows/iter; 16 iterations (compile-time).
        #pragma unroll 2
        for (int it = 0; it < 16; it++) {
            int row = it * 128 + warp * 4 + sub;
            const float4* mp = base + (size_t)row * 16 + q * 2;
            float4 m0 = mp[0];
            float4 m1 = mp[1];
            if (row < STASH_ROWS) {
                st4[row * 16 + q * 2]     = m0;
                st4[row * 16 + q * 2 + 1] = m1;
            }
            float dot = m0.x * k0.x + m0.y * k0.y + m0.z * k0.z + m0.w * k0.w
                      + m1.x * k1.x + m1.y * k1.y + m1.z * k1.z + m1.w * k1.w;
            float nrm = m0.x * m0.x + m0.y * m0.y + m0.z * m0.z + m0.w * m0.w
                      + m1.x * m1.x + m1.y * m1.y + m1.z * m1.z + m1.w * m1.w;
            #pragma unroll
            for (int o = 4; o; o >>= 1) {
                dot += __shfl_xor_sync(0xffffffffu, dot, o);
                nrm += __shfl_xor_sync(0xffffffffu, nrm, o);
            }
            if (q == 0) {
                float denom = fmaxf(sqrtf(nrm) * knorm, 1e-8f);
                s_sc[row] = beta * dot / denom;
            }
        }
    }
    __syncthreads();

    // ---- Phase 2: softmax + gate + shift + sharpen ----
    {
        float v[2];
        v[0] = s_sc[tid]; v[1] = s_sc[tid + 1024];
        float mx = fmaxf(v[0], v[1]);
        mx = blockReduce1024(mx, red, true);

        float sum = 0.f;
        #pragma unroll
        for (int i = 0; i < 2; i++) { v[i] = __expf(v[i] - mx); sum += v[i]; }
        sum = blockReduce1024(sum, red, false);
        float inv = 1.f / sum;

        float g = ssc[1];
        #pragma unroll
        for (int i = 0; i < 2; i++) {
            int idx = tid + i * 1024;
            s_w[idx] = g * (v[i] * inv) + (1.f - g) * w_prev[(size_t)b * N + idx];
        }
        __syncthreads();

        float s0 = ssc[3], s1 = ssc[4], s2 = ssc[5], gamma = ssc[2];
        float u[2];
        float psum = 0.f;
        #pragma unroll
        for (int i = 0; i < 2; i++) {
            int idx = tid + i * 1024;
            float wt = s_w[(idx + N - 1) & (N - 1)] * s0 + s_w[idx] * s1
                     + s_w[(idx + 1) & (N - 1)] * s2;
            float ws = __powf(wt, gamma);   // wt >= 0
            u[i] = ws; psum += ws;
        }
        psum = blockReduce1024(psum, red, false);
        float invp = 1.f / (psum + 1e-16f);
        #pragma unroll
        for (int i = 0; i < 2; i++) {
            int idx = tid + i * 1024;
            float wf = u[i] * invp;
            s_sc[idx] = wf;                        // final w, reuse s_sc
            w_out[(size_t)b * N + idx] = wf;
        }
    }
    __syncthreads();

    // ---- Stage B: projection rows [70,198) -> e, a (4 rows/warp) ----
    for (int j = 70 + warp; j < OUTD; j += 32) {
        float acc = wdot(Wm, j, sh_h, lane);
        if (lane == 0) {
            float v = acc + bias[j];
            if (j < 134) sea[j - 70] = sigmoid_f(v);       // e
            else         sea[64 + (j - 134)] = v;          // a
        }
    }
    __syncthreads();

    // ---- Phase 3: erase/add write ----
    {
        const float4* min4 = (const float4*)(memory + (size_t)b * N * M);
        float4* mout4 = (float4*)(mem_out + (size_t)b * N * M);
        const float4* st4 = (const float4*)stash;
        int m4 = tid & 15;
        float4 e4 = ((const float4*)sea)[m4];
        float4 a4 = ((const float4*)(sea + 64))[m4];

        // 3b FIRST: rows [STASH_ROWS, N) from global, reverse order
        // (most-recently-streamed L2 lines first), unroll 4.
        #pragma unroll 4
        for (int it = (N * M / 4) / 1024 - 1; it >= STASH_ROWS * 16 / 1024; it--) {
            int i = it * 1024 + tid;
            float wv = s_sc[i >> 4];
            float4 m = __ldcs(min4 + i);
            float4 o;
            o.x = m.x * (1.f - wv * e4.x) + wv * a4.x;
            o.y = m.y * (1.f - wv * e4.y) + wv * a4.y;
            o.z = m.z * (1.f - wv * e4.z) + wv * a4.z;
            o.w = m.w * (1.f - wv * e4.w) + wv * a4.w;
            __stcs(mout4 + i, o);
        }
        // 3a: stashed rows [0, STASH_ROWS) from smem (stable, can go last).
        #pragma unroll 4
        for (int it = 0; it < STASH_ROWS * 16 / 1024; it++) {
            int i = it * 1024 + tid;
            float wv = s_sc[i >> 4];
            float4 m = st4[i];
            float4 o;
            o.x = m.x * (1.f - wv * e4.x) + wv * a4.x;
            o.y = m.y * (1.f - wv * e4.y) + wv * a4.y;
            o.z = m.z * (1.f - wv * e4.z) + wv * a4.z;
            o.w = m.w * (1.f - wv * e4.w) + wv * a4.w;
            __stcs(mout4 + i, o);
        }
    }
}

// ---------------------------------------------------------------------------
extern "C" void kernel_launch(void* const* d_in, const int* in_sizes, int n_in,
                              void* d_out, int out_size) {
    const float* h      = (const float*)d_in[0];
    const float* w_prev = (const float*)d_in[1];
    const float* memory = (const float*)d_in[2];
    const float* Wm     = (const float*)d_in[3];
    const float* bias   = (const float*)d_in[4];

    float* w_out   = (float*)d_out;                     // [B, N]
    float* mem_out = (float*)d_out + (size_t)B * N;     // [B, N, M]

    const int stash_bytes = STASH_ROWS * M * sizeof(float);   // 160 KB
    static bool attr_set = false;
    if (!attr_set) {
        cudaFuncSetAttribute(k_all, cudaFuncAttributeMaxDynamicSharedMemorySize,
                             stash_bytes);
        attr_set = true;
    }
    k_all<<<B, 1024, stash_bytes>>>(h, w_prev, memory, Wm, bias, w_out, mem_out);
}